// round 7
// baseline (speedup 1.0000x reference)
#include <cuda_runtime.h>

// Closed form (derived R0): theta_i = x[b,i]+w[i], c_i = cos(2*theta_i)
//   out[b] = { c1*c2*c3, c0*c1, c0*c1*c2, c0*c1*c2*c3 }
//
// R7: 256-bit global loads/stores (Blackwell LDG.E.256/STG.E.256 via
// ld/st.global.v8.f32). Halves LDG+STG instruction count and L1tex
// wavefronts; doubles bytes-in-flight per scoreboard slot. Each 32B chunk
// = 2 batch elements. 2048 CTAs x 128 thr x 4 chunks.

#define NTHREADS 128
#define NBLOCKS  2048
#define CHUNKS   4
#define TOTAL    2097152                          // batch (float4 count)
#define TOTAL8   (TOTAL / 2)                      // 32B-chunk count = 1048576
// per-CTA: NTHREADS*CHUNKS = 512 chunks; NBLOCKS*512 = 1048576 ✓

struct F8 { float v[8]; };

__device__ __forceinline__ void ldg256(const float* __restrict__ p, F8& r)
{
    asm volatile("ld.global.nc.v8.f32 {%0,%1,%2,%3,%4,%5,%6,%7}, [%8];"
                 : "=f"(r.v[0]), "=f"(r.v[1]), "=f"(r.v[2]), "=f"(r.v[3]),
                   "=f"(r.v[4]), "=f"(r.v[5]), "=f"(r.v[6]), "=f"(r.v[7])
                 : "l"(p));
}

__device__ __forceinline__ void stg256(float* __restrict__ p, const F8& r)
{
    asm volatile("st.global.v8.f32 [%0], {%1,%2,%3,%4,%5,%6,%7,%8};"
                 :: "l"(p),
                    "f"(r.v[0]), "f"(r.v[1]), "f"(r.v[2]), "f"(r.v[3]),
                    "f"(r.v[4]), "f"(r.v[5]), "f"(r.v[6]), "f"(r.v[7])
                 : "memory");
}

// process two batch elements packed in one 32B chunk
__device__ __forceinline__ F8 proc2(const F8& x, float w0, float w1,
                                    float w2, float w3)
{
    F8 o;
#pragma unroll
    for (int e = 0; e < 2; e++) {
        float c0 = __cosf(fmaf(2.0f, x.v[4*e+0], w0));
        float c1 = __cosf(fmaf(2.0f, x.v[4*e+1], w1));
        float c2 = __cosf(fmaf(2.0f, x.v[4*e+2], w2));
        float c3 = __cosf(fmaf(2.0f, x.v[4*e+3], w3));
        float t01  = c0 * c1;
        float t012 = t01 * c2;
        o.v[4*e+0] = c1 * c2 * c3;
        o.v[4*e+1] = t01;
        o.v[4*e+2] = t012;
        o.v[4*e+3] = t012 * c3;
    }
    return o;
}

__global__ void __launch_bounds__(NTHREADS)
hilbert_v8(const float* __restrict__ x,
           const float* __restrict__ w,
           float* __restrict__ out)
{
    int tx   = threadIdx.x;
    long base = (long)blockIdx.x * (NTHREADS * CHUNKS) ;  // in 32B chunks

    float w0 = 2.0f * w[0], w1 = 2.0f * w[1];
    float w2 = 2.0f * w[2], w3 = 2.0f * w[3];

    // front-batched 256-bit loads: 4 x 32B in flight per thread
    F8 a0, a1, a2, a3;
    ldg256(x + (base + 0 * NTHREADS + tx) * 8, a0);
    ldg256(x + (base + 1 * NTHREADS + tx) * 8, a1);
    ldg256(x + (base + 2 * NTHREADS + tx) * 8, a2);
    ldg256(x + (base + 3 * NTHREADS + tx) * 8, a3);

    F8 o0 = proc2(a0, w0, w1, w2, w3);
    stg256(out + (base + 0 * NTHREADS + tx) * 8, o0);
    F8 o1 = proc2(a1, w0, w1, w2, w3);
    stg256(out + (base + 1 * NTHREADS + tx) * 8, o1);
    F8 o2 = proc2(a2, w0, w1, w2, w3);
    stg256(out + (base + 2 * NTHREADS + tx) * 8, o2);
    F8 o3 = proc2(a3, w0, w1, w2, w3);
    stg256(out + (base + 3 * NTHREADS + tx) * 8, o3);
}

// Generic fallback (any n of float4s).
__device__ __forceinline__ float4 proc(float4 xv, float w0, float w1,
                                       float w2, float w3)
{
    float c0 = __cosf(fmaf(2.0f, xv.x, w0));
    float c1 = __cosf(fmaf(2.0f, xv.y, w1));
    float c2 = __cosf(fmaf(2.0f, xv.z, w2));
    float c3 = __cosf(fmaf(2.0f, xv.w, w3));
    float t01  = c0 * c1;
    float t012 = t01 * c2;
    float4 o;
    o.x = c1 * c2 * c3;
    o.y = t01;
    o.z = t012;
    o.w = t012 * c3;
    return o;
}

__global__ void __launch_bounds__(256)
hilbert_generic(const float4* __restrict__ x4,
                const float* __restrict__ w,
                float4* __restrict__ out4, int n)
{
    int i = blockIdx.x * blockDim.x + threadIdx.x;
    if (i >= n) return;
    float w0 = 2.0f * w[0], w1 = 2.0f * w[1];
    float w2 = 2.0f * w[2], w3 = 2.0f * w[3];
    out4[i] = proc(x4[i], w0, w1, w2, w3);
}

extern "C" void kernel_launch(void* const* d_in, const int* in_sizes, int n_in,
                              void* d_out, int out_size)
{
    const float* x = (const float*)d_in[0];
    const float* w = (const float*)d_in[1];
    int nx = in_sizes[0];
    if (n_in >= 2 && in_sizes[0] < in_sizes[1]) {
        x = (const float*)d_in[1];
        w = (const float*)d_in[0];
        nx = in_sizes[1];
    }

    int n = nx / 4;  // float4 count (= batch)

    if (n == TOTAL) {
        hilbert_v8<<<NBLOCKS, NTHREADS>>>(x, w, (float*)d_out);
    } else {
        int threads = 256;
        int blocks = (n + threads - 1) / threads;
        hilbert_generic<<<blocks, threads>>>(
            (const float4*)x, w, (float4*)d_out, n);
    }
}

// round 8
// speedup vs baseline: 1.0269x; 1.0269x over previous
#include <cuda_runtime.h>

// Closed form (derived R0): theta_i = x[b,i]+w[i], c_i = cos(2*theta_i)
//   out[b] = { c1*c2*c3, c0*c1, c0*c1*c2, c0*c1*c2*c3 }
//
// R8: opposite end of the work-per-thread axis. 2^21 threads, ONE float4
// each, ~12 regs, no loops. 8192 CTAs stream through the SMs in fine-grained
// waves so the HW scheduler smooths L2-latency variance by queue depth
// instead of per-warp MLP. Five mid-granularity designs all hit 10.7-11.0us;
// this is the decisive floor test.

__device__ __forceinline__ float4 proc(float4 xv, float w0, float w1,
                                       float w2, float w3)
{
    float c0 = __cosf(fmaf(2.0f, xv.x, w0));
    float c1 = __cosf(fmaf(2.0f, xv.y, w1));
    float c2 = __cosf(fmaf(2.0f, xv.z, w2));
    float c3 = __cosf(fmaf(2.0f, xv.w, w3));
    float t01  = c0 * c1;
    float t012 = t01 * c2;
    float4 o;
    o.x = c1 * c2 * c3;
    o.y = t01;
    o.z = t012;
    o.w = t012 * c3;
    return o;
}

__global__ void __launch_bounds__(256)
hilbert_flat(const float4* __restrict__ x4,
             const float* __restrict__ w,
             float4* __restrict__ out4, int n)
{
    int i = blockIdx.x * blockDim.x + threadIdx.x;
    if (i >= n) return;
    float w0 = 2.0f * w[0], w1 = 2.0f * w[1];
    float w2 = 2.0f * w[2], w3 = 2.0f * w[3];
    out4[i] = proc(x4[i], w0, w1, w2, w3);
}

extern "C" void kernel_launch(void* const* d_in, const int* in_sizes, int n_in,
                              void* d_out, int out_size)
{
    const float* x = (const float*)d_in[0];
    const float* w = (const float*)d_in[1];
    int nx = in_sizes[0];
    if (n_in >= 2 && in_sizes[0] < in_sizes[1]) {
        x = (const float*)d_in[1];
        w = (const float*)d_in[0];
        nx = in_sizes[1];
    }

    int n = nx / 4;  // float4 count (= batch)
    int threads = 256;
    int blocks = (n + threads - 1) / threads;   // 8192 for BATCH=2^21

    hilbert_flat<<<blocks, threads>>>(
        (const float4*)x, w, (float4*)d_out, n);
}